// round 12
// baseline (speedup 1.0000x reference)
#include <cuda_runtime.h>
#include <cuda_bf16.h>
#include <cstdint>

#define HID   2048
#define KSEL  256
#define NTOK  16384
#define NTHR  256
#define FULLW 0xFFFFFFFFu

__device__ int g_ids64;

// Detect int32 vs int64 ids (odd 32-bit words all zero => int64).
__global__ void detect_ids_kernel(const unsigned int* __restrict__ w) {
    __shared__ unsigned acc[NTHR];
    unsigned v = 0;
    for (int i = threadIdx.x; i < NTOK / 2; i += NTHR) v |= w[2 * i + 1];
    acc[threadIdx.x] = v;
    __syncthreads();
    for (int s = NTHR / 2; s > 0; s >>= 1) {
        if (threadIdx.x < s) acc[threadIdx.x] |= acc[threadIdx.x + s];
        __syncthreads();
    }
    if (threadIdx.x == 0) g_ids64 = (acc[0] == 0u) ? 1 : 0;
}

__device__ __forceinline__ unsigned f2key(float f) {
    unsigned u = __float_as_uint(f);
    return u ^ ((u & 0x80000000u) ? 0xFFFFFFFFu : 0x80000000u);
}
__device__ __forceinline__ float key2f(unsigned u) {
    unsigned b = (u & 0x80000000u) ? (u ^ 0x80000000u) : ~u;
    return __uint_as_float(b);
}

struct SmemT {
    unsigned ctr[2048];              // 8KB: histogram -> posBase -> scatter cursor
    unsigned long long sk[KSEL];     // 2KB: survivors grouped by bin segment
    unsigned candKey[2048];          // 8KB: threshold-bin candidate keys
    unsigned short candIdx[2048];    // 4KB: threshold-bin candidate indices
    float outV[KSEL];                // 1KB
    float outI[KSEL];                // 1KB
    unsigned warpTot[8];
    unsigned s_b, s_rem;
    unsigned cntN;
};  // ~24.3KB -> 8 CTAs/SM

__global__ __launch_bounds__(NTHR, 8) void topk_kernel(
    const void* __restrict__ ids_raw,
    const float* __restrict__ W,
    float* __restrict__ out_val,
    float* __restrict__ out_idx)
{
    __shared__ SmemT s;
    const int tok  = blockIdx.x;
    const int tid  = threadIdx.x;
    const int lane = tid & 31;
    const int wrp  = tid >> 5;

    if (tid == 0) s.cntN = 0u;

    // ---- gather one embedding row (coalesced float4) ----
    long long id;
    if (g_ids64) id = ((const long long*)ids_raw)[tok];
    else         id = (long long)((const int*)ids_raw)[tok];

    const float4* row = (const float4*)(W + (size_t)id * HID);
    float4 a = __ldg(row + tid);
    float4 b = __ldg(row + tid + NTHR);

    unsigned key[8];
    key[0] = f2key(a.x); key[1] = f2key(a.y); key[2] = f2key(a.z); key[3] = f2key(a.w);
    key[4] = f2key(b.x); key[5] = f2key(b.y); key[6] = f2key(b.z); key[7] = f2key(b.w);

    // ---- 11-bit histogram over the top bits (plain atomics) ----
    uint4 z = make_uint4(0u, 0u, 0u, 0u);
    ((uint4*)s.ctr)[tid]        = z;
    ((uint4*)s.ctr)[tid + NTHR] = z;
    __syncthreads();

    #pragma unroll
    for (int e = 0; e < 8; e++)
        atomicAdd(&s.ctr[key[e] >> 21], 1u);
    __syncthreads();

    // ---- suffix scan: posBase per bin + locate threshold bin ----
    uint4 h0 = ((uint4*)s.ctr)[tid * 2];
    uint4 h1 = ((uint4*)s.ctr)[tid * 2 + 1];
    unsigned bins[8] = {h0.x, h0.y, h0.z, h0.w, h1.x, h1.y, h1.z, h1.w};
    unsigned tsum = 0;
    #pragma unroll
    for (int i = 0; i < 8; i++) tsum += bins[i];

    unsigned sfx = tsum;                        // sum over lanes >= mine
    #pragma unroll
    for (int off = 1; off < 32; off <<= 1) {
        unsigned y = __shfl_down_sync(FULLW, sfx, off);
        if (lane + off < 32) sfx += y;
    }
    if (lane == 0) s.warpTot[wrp] = sfx;
    __syncthreads();

    unsigned hiW = 0;
    #pragma unroll
    for (int w = 0; w < 8; w++) hiW += (w > wrp) ? s.warpTot[w] : 0u;

    unsigned run = hiW + (sfx - tsum);          // count in bins above my top bin
    unsigned pb[8];
    #pragma unroll
    for (int i = 7; i >= 0; i--) {
        unsigned h = bins[i];
        pb[i] = run;                            // posBase for bin tid*8+i
        if (run < KSEL && KSEL <= run + h) {
            s.s_b   = (unsigned)(tid * 8 + i);
            s.s_rem = KSEL - run;
        }
        run += h;
    }
    // Seed scatter cursors with posBase (ctr only; no cum array needed:
    // after scatter, posBase[d] == ctr[d+1] for every survivor digit d).
    ((uint4*)s.ctr)[tid * 2]     = make_uint4(pb[0], pb[1], pb[2], pb[3]);
    ((uint4*)s.ctr)[tid * 2 + 1] = make_uint4(pb[4], pb[5], pb[6], pb[7]);
    __syncthreads();

    const unsigned bsel = s.s_b;
    const unsigned rem  = s.s_rem;              // 1..count(threshold bin)
    const int      nG   = (int)(KSEL - rem);    // survivors strictly above

    // ---- scatter: only elements with d >= bsel do an atomic (~256+n1) ----
    #pragma unroll
    for (int e = 0; e < 8; e++) {
        unsigned k = key[e];
        unsigned d = k >> 21;
        if (d < bsel) continue;
        int idx = (e < 4) ? (tid * 4 + e) : ((tid + NTHR) * 4 + (e - 4));
        if (d > bsel) {
            unsigned slot = atomicAdd(&s.ctr[d], 1u);   // within-bin contention ~3
            s.sk[slot] = ((unsigned long long)k << 32) | (unsigned)(~idx);
        } else {
            unsigned slot = atomicAdd(&s.cntN, 1u);
            s.candKey[slot] = k;
            s.candIdx[slot] = (unsigned short)idx;
        }
    }
    __syncthreads();

    const int n1 = (int)s.cntN;

    // ---- survivors: rank within own bin segment [ctr[d+1], ctr[d]) ----
    if (tid < nG) {
        unsigned long long my = s.sk[tid];
        const unsigned d = (unsigned)(my >> 53);
        unsigned lo = (d == 2047u) ? 0u : s.ctr[d + 1];
        unsigned hi = s.ctr[d];
        int rank = 0;
        for (unsigned j = lo; j < hi; j++)
            rank += (s.sk[j] > my);
        s.outV[lo + rank] = key2f((unsigned)(my >> 32));
        s.outI[lo + rank] = (float)((int)(~(unsigned)my));
    }

    // ---- threshold bin: exact rank-select top `rem` into slots [nG, 256) ----
    for (int t = tid; t < n1; t += NTHR) {
        unsigned myk = s.candKey[t];
        unsigned myi = s.candIdx[t];
        int rank = 0;
        for (int j = 0; j < n1; j++) {
            unsigned ck = s.candKey[j];
            unsigned ci = s.candIdx[j];
            rank += (ck > myk) || (ck == myk && ci < myi);
        }
        if (rank < (int)rem) {
            s.outV[nG + rank] = key2f(myk);
            s.outI[nG + rank] = (float)(int)myi;
        }
    }
    __syncthreads();

    // ---- single fully-coalesced global write ----
    float* ov = out_val + (size_t)tok * KSEL;
    float* oi = out_idx + (size_t)tok * KSEL;
    ov[tid] = s.outV[tid];
    oi[tid] = s.outI[tid];
}

extern "C" void kernel_launch(void* const* d_in, const int* in_sizes, int n_in,
                              void* d_out, int out_size)
{
    const void*  ids = d_in[0];
    const float* W   = (const float*)d_in[1];

    float* out_val = (float*)d_out;
    float* out_idx = (float*)d_out + (size_t)NTOK * KSEL;

    detect_ids_kernel<<<1, NTHR>>>((const unsigned int*)ids);
    topk_kernel<<<NTOK, NTHR>>>(ids, W, out_val, out_idx);
}

// round 13
// speedup vs baseline: 1.1835x; 1.1835x over previous
#include <cuda_runtime.h>
#include <cuda_bf16.h>
#include <cstdint>

#define HID   2048
#define KSEL  256
#define NTOK  16384
#define NTHR  256
#define FULLW 0xFFFFFFFFu
// f2key(0.5f): bin-aligned filter (low 21 bits zero) => bin(key)>=bin(THR0)
#define THR0  0xBF000000u
#define SENT  0xFFFFFFFFu

__device__ int g_ids64;

// Detect int32 vs int64 ids (odd 32-bit words all zero => int64).
__global__ void detect_ids_kernel(const unsigned int* __restrict__ w) {
    __shared__ unsigned acc[NTHR];
    unsigned v = 0;
    for (int i = threadIdx.x; i < NTOK / 2; i += NTHR) v |= w[2 * i + 1];
    acc[threadIdx.x] = v;
    __syncthreads();
    for (int s = NTHR / 2; s > 0; s >>= 1) {
        if (threadIdx.x < s) acc[threadIdx.x] |= acc[threadIdx.x + s];
        __syncthreads();
    }
    if (threadIdx.x == 0) g_ids64 = (acc[0] == 0u) ? 1 : 0;
}

__device__ __forceinline__ unsigned f2key(float f) {
    unsigned u = __float_as_uint(f);
    return u ^ ((u & 0x80000000u) ? 0xFFFFFFFFu : 0x80000000u);
}
__device__ __forceinline__ float key2f(unsigned u) {
    unsigned b = (u & 0x80000000u) ? (u ^ 0x80000000u) : ~u;
    return __uint_as_float(b);
}

struct SmemT {
    unsigned ctr[2048];              // 8KB: histogram -> scatter cursors
    unsigned long long sk[KSEL];     // 2KB: survivors grouped by bin segment
    unsigned cand[2048];             // 8KB: packed threshold-bin candidates
    float2 outVI[KSEL];              // 2KB: staged (value, index) pairs
    unsigned warpTot[8];
    unsigned s_b, s_rem;
    unsigned cntN;
};  // ~20.3KB

__global__ __launch_bounds__(NTHR, 6) void topk_kernel(
    const void* __restrict__ ids_raw,
    const float* __restrict__ W,
    float* __restrict__ out_val,
    float* __restrict__ out_idx)
{
    __shared__ SmemT s;
    const int tok  = blockIdx.x;
    const int tid  = threadIdx.x;
    const int lane = tid & 31;
    const int wrp  = tid >> 5;

    if (tid == 0) { s.cntN = 0u; s.s_b = SENT; }

    // ---- gather one embedding row (coalesced float4) ----
    long long id;
    if (g_ids64) id = ((const long long*)ids_raw)[tok];
    else         id = (long long)((const int*)ids_raw)[tok];

    const float4* row = (const float4*)(W + (size_t)id * HID);
    float4 a = __ldg(row + tid);
    float4 b = __ldg(row + tid + NTHR);

    unsigned key[8];
    key[0] = f2key(a.x); key[1] = f2key(a.y); key[2] = f2key(a.z); key[3] = f2key(a.w);
    key[4] = f2key(b.x); key[5] = f2key(b.y); key[6] = f2key(b.z); key[7] = f2key(b.w);

    // ---- filtered 11-bit histogram + scan, with exact rare fallback ----
    unsigned thr = THR0;
    unsigned pb[8];
    for (;;) {
        uint4 z = make_uint4(0u, 0u, 0u, 0u);
        ((uint4*)s.ctr)[tid]        = z;
        ((uint4*)s.ctr)[tid + NTHR] = z;
        __syncthreads();

        #pragma unroll
        for (int e = 0; e < 8; e++)
            if (key[e] >= thr) atomicAdd(&s.ctr[key[e] >> 21], 1u);
        __syncthreads();

        // suffix scan over 2048 bins
        uint4 h0 = ((uint4*)s.ctr)[tid * 2];
        uint4 h1 = ((uint4*)s.ctr)[tid * 2 + 1];
        unsigned bins[8] = {h0.x, h0.y, h0.z, h0.w, h1.x, h1.y, h1.z, h1.w};
        unsigned tsum = 0;
        #pragma unroll
        for (int i = 0; i < 8; i++) tsum += bins[i];

        unsigned sfx = tsum;                    // sum over lanes >= mine
        #pragma unroll
        for (int off = 1; off < 32; off <<= 1) {
            unsigned y = __shfl_down_sync(FULLW, sfx, off);
            if (lane + off < 32) sfx += y;
        }
        if (lane == 0) s.warpTot[wrp] = sfx;
        __syncthreads();

        unsigned hiW = 0;
        #pragma unroll
        for (int w = 0; w < 8; w++) hiW += (w > wrp) ? s.warpTot[w] : 0u;

        unsigned run = hiW + (sfx - tsum);      // counted in bins above my top bin
        #pragma unroll
        for (int i = 7; i >= 0; i--) {
            unsigned h = bins[i];
            pb[i] = run;                        // posBase for bin tid*8+i
            if (run < KSEL && KSEL <= run + h) {
                s.s_b   = (unsigned)(tid * 8 + i);
                s.s_rem = KSEL - run;
            }
            run += h;
        }
        __syncthreads();

        if (s.s_b != SENT) break;               // found (always, unless <256 pass filter)
        thr = 0u;                               // astronomically rare exact fallback
    }

    // Seed scatter cursors with posBase (posBase[d] == ctr[d+1] after scatter).
    ((uint4*)s.ctr)[tid * 2]     = make_uint4(pb[0], pb[1], pb[2], pb[3]);
    ((uint4*)s.ctr)[tid * 2 + 1] = make_uint4(pb[4], pb[5], pb[6], pb[7]);
    __syncthreads();

    const unsigned bsel = s.s_b;
    const unsigned rem  = s.s_rem;              // 1..count(threshold bin)
    const int      nG   = (int)(KSEL - rem);    // survivors strictly above

    // ---- scatter: only elements with d >= bsel do an atomic (~256+n1) ----
    #pragma unroll
    for (int e = 0; e < 8; e++) {
        unsigned k = key[e];
        unsigned d = k >> 21;
        if (d < bsel) continue;
        int idx = (e < 4) ? (tid * 4 + e) : ((tid + NTHR) * 4 + (e - 4));
        if (d > bsel) {
            unsigned slot = atomicAdd(&s.ctr[d], 1u);   // within-bin contention ~3
            s.sk[slot] = ((unsigned long long)k << 32) | (unsigned)(~idx);
        } else {
            unsigned slot = atomicAdd(&s.cntN, 1u);
            // all candidates share top-11 bits: pack low21(key) + inverted idx
            s.cand[slot] = ((k & 0x1FFFFFu) << 11) | (0x7FFu ^ (unsigned)idx);
        }
    }
    __syncthreads();

    const int n1 = (int)s.cntN;

    // ---- survivors: rank within own bin segment [ctr[d+1], ctr[d]) ----
    if (tid < nG) {
        unsigned long long my = s.sk[tid];
        const unsigned d = (unsigned)(my >> 53);
        unsigned lo = (d == 2047u) ? 0u : s.ctr[d + 1];
        unsigned hi = s.ctr[d];
        int rank = 0;
        for (unsigned j = lo; j < hi; j++)
            rank += (s.sk[j] > my);
        s.outVI[lo + rank] = make_float2(key2f((unsigned)(my >> 32)),
                                         (float)((int)(~(unsigned)my)));
    }

    // ---- threshold bin: rank-select top `rem` into slots [nG, 256) ----
    for (int t = tid; t < n1; t += NTHR) {
        unsigned my = s.cand[t];
        int rank = 0;
        for (int j = 0; j < n1; j++) rank += (s.cand[j] > my);
        if (rank < (int)rem) {
            unsigned k   = (bsel << 21) | (my >> 11);
            unsigned idx = 0x7FFu ^ (my & 0x7FFu);
            s.outVI[nG + rank] = make_float2(key2f(k), (float)idx);
        }
    }
    __syncthreads();

    // ---- single fully-coalesced global write ----
    float2 r = s.outVI[tid];
    out_val[(size_t)tok * KSEL + tid] = r.x;
    out_idx[(size_t)tok * KSEL + tid] = r.y;
}

extern "C" void kernel_launch(void* const* d_in, const int* in_sizes, int n_in,
                              void* d_out, int out_size)
{
    const void*  ids = d_in[0];
    const float* W   = (const float*)d_in[1];

    float* out_val = (float*)d_out;
    float* out_idx = (float*)d_out + (size_t)NTOK * KSEL;

    detect_ids_kernel<<<1, NTHR>>>((const unsigned int*)ids);
    topk_kernel<<<NTOK, NTHR>>>(ids, W, out_val, out_idx);
}